// round 1
// baseline (speedup 1.0000x reference)
#include <cuda_runtime.h>
#include <math.h>

#define BB 64        // batch
#define TT 512       // seq len
#define HH 256       // hidden
#define G4 1024      // 4*H
#define NCLS 20
#define NCTAS_B 128  // persistent CTAs for phase B

// Scratch (static device globals — no runtime allocation)
__device__ float g_xz[(size_t)BB * TT * G4];   // 128 MB
__device__ float g_hbuf[2][BB * HH];
__device__ unsigned g_arrived;
__device__ unsigned g_release;

// ---------------------------------------------------------------------------
// Phase A: xz[b,t,:] = emb[x[b,t]] @ W + bias      (M=32768, K=256, N=1024)
// Classic 64x64 tile, 256 threads, 4x4 micro-tile, embedding gather for A rows.
// ---------------------------------------------------------------------------
__global__ __launch_bounds__(256) void phaseA_kernel(
    const int* __restrict__ x, const float* __restrict__ emb,
    const float* __restrict__ W, const float* __restrict__ bias)
{
    __shared__ float As[16][68];
    __shared__ float Bs[16][68];
    __shared__ int ridx[64];

    const int tid = threadIdx.x;
    const int bx = blockIdx.x;   // 0..15  (col block)
    const int by = blockIdx.y;   // 0..511 (row block)

    if (tid < 64) ridx[tid] = x[by * 64 + tid];
    __syncthreads();

    const int tx = tid & 15;   // 0..15 col group
    const int ty = tid >> 4;   // 0..15 row group

    float acc[4][4];
#pragma unroll
    for (int i = 0; i < 4; i++)
#pragma unroll
        for (int j = 0; j < 4; j++) acc[i][j] = 0.f;

    for (int k0 = 0; k0 < 256; k0 += 16) {
        // A tile: 64 rows x 16 k
        {
            int r  = tid >> 2;
            int kq = (tid & 3) << 2;
            float4 v = *(const float4*)(emb + (size_t)ridx[r] * 256 + k0 + kq);
            As[kq + 0][r] = v.x; As[kq + 1][r] = v.y;
            As[kq + 2][r] = v.z; As[kq + 3][r] = v.w;
            // B tile: 16 k x 64 cols
            int kk = tid >> 4;
            int c4 = (tid & 15) << 2;
            *(float4*)&Bs[kk][c4] =
                *(const float4*)(W + (size_t)(k0 + kk) * G4 + bx * 64 + c4);
        }
        __syncthreads();
#pragma unroll
        for (int k = 0; k < 16; k++) {
            float4 av = *(const float4*)&As[k][ty << 2];
            float4 bv = *(const float4*)&Bs[k][tx << 2];
            float a[4] = {av.x, av.y, av.z, av.w};
            float b[4] = {bv.x, bv.y, bv.z, bv.w};
#pragma unroll
            for (int i = 0; i < 4; i++)
#pragma unroll
                for (int j = 0; j < 4; j++)
                    acc[i][j] = fmaf(a[i], b[j], acc[i][j]);
        }
        __syncthreads();
    }

    const int colbase = bx * 64 + (tx << 2);
    float4 bv = *(const float4*)(bias + colbase);
#pragma unroll
    for (int i = 0; i < 4; i++) {
        int row = by * 64 + (ty << 2) + i;
        float4 o = make_float4(acc[i][0] + bv.x, acc[i][1] + bv.y,
                               acc[i][2] + bv.z, acc[i][3] + bv.w);
        *(float4*)(g_xz + (size_t)row * G4 + colbase) = o;
    }
}

// ---------------------------------------------------------------------------
// Phase B: 512 sequential LSTM steps, persistent grid (128 CTAs) + global
// barrier per step. CTA (jgrp, bgrp) owns 16 batches x 8 hidden cols.
// U slice (32 gate-cols x 256) lives in smem for the whole kernel.
// h ping-pongs through L2 (__ldcg / write-through STG).
// ---------------------------------------------------------------------------
#define UT_STRIDE 260   // 1040 B  (== 16 mod 128: conflict-free adjacent rows)
#define SMEM_B ((32 * UT_STRIDE + 16 * UT_STRIDE) * 4)

extern __shared__ float sdyn[];

__global__ __launch_bounds__(128, 1) void phaseB_kernel(const float* __restrict__ U)
{
    float* Ut = sdyn;                    // [32][260]  U^T slice
    float* hs = sdyn + 32 * UT_STRIDE;   // [16][260]  h stage

    const int tid  = threadIdx.x;        // 128
    const int jgrp = blockIdx.x;         // 0..31
    const int bgrp = blockIdx.y;         // 0..3

    // Stage U^T once: local col cl = g*8+jl  ->  global col g*256 + jgrp*8 + jl
    for (int i = tid; i < 32 * 256; i += 128) {
        int cl = i >> 8, k = i & 255;
        int g = cl >> 3, jl = cl & 7;
        Ut[cl * UT_STRIDE + k] = U[(size_t)k * G4 + g * HH + jgrp * 8 + jl];
    }

    const int bl = tid >> 3;             // 0..15
    const int jl = tid & 7;              // 0..7
    const int b  = bgrp * 16 + bl;
    const int j  = jgrp * 8 + jl;

    float c = 0.f;
    const float* xzp = g_xz + (size_t)b * TT * G4 + j;

    const float4* u0 = (const float4*)(Ut + (0 * 8 + jl) * UT_STRIDE);
    const float4* u1 = (const float4*)(Ut + (1 * 8 + jl) * UT_STRIDE);
    const float4* u2 = (const float4*)(Ut + (2 * 8 + jl) * UT_STRIDE);
    const float4* u3 = (const float4*)(Ut + (3 * 8 + jl) * UT_STRIDE);
    const float4* hrow = (const float4*)(hs + bl * UT_STRIDE);

    __syncthreads();   // Ut ready

    for (int t = 0; t < TT; t++) {
        // prefetch xz for this step (independent of barrier)
        const float* xr = xzp + (size_t)t * G4;
        float a0 = __ldg(xr + 0 * HH);
        float a1 = __ldg(xr + 1 * HH);
        float a2 = __ldg(xr + 2 * HH);
        float a3 = __ldg(xr + 3 * HH);

        // stage h (16 rows x 256) from the ping-pong buffer, L1-bypassed
        const float* hsrc = g_hbuf[t & 1] + bgrp * 16 * HH;
        for (int i = tid * 4; i < 16 * HH; i += 128 * 4) {
            int r = i >> 8, k = i & 255;
            float4 v = __ldcg((const float4*)(hsrc + r * HH + k));
            *(float4*)(hs + r * UT_STRIDE + k) = v;
        }
        __syncthreads();

#pragma unroll 8
        for (int k4 = 0; k4 < 64; k4++) {
            float4 hv = hrow[k4];
            float4 v0 = u0[k4];
            float4 v1 = u1[k4];
            float4 v2 = u2[k4];
            float4 v3 = u3[k4];
            a0 = fmaf(hv.x, v0.x, a0); a0 = fmaf(hv.y, v0.y, a0);
            a0 = fmaf(hv.z, v0.z, a0); a0 = fmaf(hv.w, v0.w, a0);
            a1 = fmaf(hv.x, v1.x, a1); a1 = fmaf(hv.y, v1.y, a1);
            a1 = fmaf(hv.z, v1.z, a1); a1 = fmaf(hv.w, v1.w, a1);
            a2 = fmaf(hv.x, v2.x, a2); a2 = fmaf(hv.y, v2.y, a2);
            a2 = fmaf(hv.z, v2.z, a2); a2 = fmaf(hv.w, v2.w, a2);
            a3 = fmaf(hv.x, v3.x, a3); a3 = fmaf(hv.y, v3.y, a3);
            a3 = fmaf(hv.z, v3.z, a3); a3 = fmaf(hv.w, v3.w, a3);
        }

        // gates (order i, f, c(g), o)
        float ig = 1.f / (1.f + __expf(-a0));
        float fg = 1.f / (1.f + __expf(-a1));
        float gg = tanhf(a2);
        float og = 1.f / (1.f + __expf(-a3));
        c = fmaf(fg, c, ig * gg);
        float hn = og * tanhf(c);

        g_hbuf[(t + 1) & 1][b * HH + j] = hn;   // write-through to L2

        __syncthreads();
        if (tid == 0) {
            __threadfence();
            unsigned epoch = (unsigned)(t + 1);
            unsigned prev  = atomicAdd(&g_arrived, 1u);
            if (prev + 1u == epoch * (unsigned)NCTAS_B) {
                __threadfence();
                *(volatile unsigned*)&g_release = epoch;
            } else {
                while (*(volatile unsigned*)&g_release < epoch) { }
                __threadfence();
            }
        }
        __syncthreads();
    }
}

// ---------------------------------------------------------------------------
// Phase C: logits = h_T @ Wd + bd; softmax. One warp per batch row.
// Final h lives in g_hbuf[0] (after 512 steps, (511+1)&1 == 0).
// ---------------------------------------------------------------------------
__global__ __launch_bounds__(32) void phaseC_kernel(
    const float* __restrict__ Wd, const float* __restrict__ bd,
    float* __restrict__ out)
{
    const int b = blockIdx.x;
    const int lane = threadIdx.x;
    const float* h = g_hbuf[0] + b * HH;

    float v = 0.f;
    if (lane < NCLS) {
#pragma unroll 8
        for (int k = 0; k < HH; k++)
            v = fmaf(h[k], Wd[k * NCLS + lane], v);
        v += bd[lane];
    }
    float m = (lane < NCLS) ? v : -1e30f;
#pragma unroll
    for (int o = 16; o; o >>= 1) m = fmaxf(m, __shfl_xor_sync(0xffffffffu, m, o));
    float e = (lane < NCLS) ? __expf(v - m) : 0.f;
    float s = e;
#pragma unroll
    for (int o = 16; o; o >>= 1) s += __shfl_xor_sync(0xffffffffu, s, o);
    if (lane < NCLS) out[b * NCLS + lane] = e / s;
}

// ---------------------------------------------------------------------------
extern "C" void kernel_launch(void* const* d_in, const int* in_sizes, int n_in,
                              void* d_out, int out_size)
{
    const int*   x    = (const int*)d_in[0];
    const float* emb  = (const float*)d_in[1];
    const float* W    = (const float*)d_in[2];
    const float* U    = (const float*)d_in[3];
    const float* bias = (const float*)d_in[4];
    const float* Wd   = (const float*)d_in[5];
    const float* bd   = (const float*)d_in[6];
    float* out = (float*)d_out;

    static void* hbuf_ptr = nullptr;
    static void* arr_ptr  = nullptr;
    static void* rel_ptr  = nullptr;
    static bool inited = false;
    if (!inited) {
        cudaGetSymbolAddress(&hbuf_ptr, g_hbuf);
        cudaGetSymbolAddress(&arr_ptr, g_arrived);
        cudaGetSymbolAddress(&rel_ptr, g_release);
        cudaFuncSetAttribute(phaseB_kernel,
                             cudaFuncAttributeMaxDynamicSharedMemorySize, SMEM_B);
        inited = true;
    }

    // Reset cross-launch state (graph-capturable memset nodes)
    cudaMemsetAsync(hbuf_ptr, 0, sizeof(float) * 2 * BB * HH, 0);
    cudaMemsetAsync(arr_ptr, 0, sizeof(unsigned), 0);
    cudaMemsetAsync(rel_ptr, 0, sizeof(unsigned), 0);

    phaseA_kernel<<<dim3(16, 512), 256>>>(x, emb, W, bias);
    phaseB_kernel<<<dim3(32, 4), 128, SMEM_B>>>(U);
    phaseC_kernel<<<BB, 32>>>(Wd, bd, out);
}

// round 2
// speedup vs baseline: 1.1973x; 1.1973x over previous
#include <cuda_runtime.h>
#include <math.h>

#define BB 64        // batch
#define TT 512       // seq len
#define HH 256       // hidden
#define G4 1024      // 4*H
#define NCLS 20

// Scratch (static device globals — no runtime allocation)
__device__ float g_xz[(size_t)BB * TT * G4];   // 128 MB
__device__ float g_hbuf[2][BB * HH];
__device__ unsigned g_flag[4][32 * 32];        // flag (bgrp, jgrp) at [bgrp][jgrp*32]

// ---------------------------------------------------------------------------
// packed fp32x2 helpers
// ---------------------------------------------------------------------------
__device__ __forceinline__ unsigned long long ffma2(unsigned long long a,
                                                    unsigned long long b,
                                                    unsigned long long c) {
    unsigned long long d;
    asm("fma.rn.f32x2 %0, %1, %2, %3;" : "=l"(d) : "l"(a), "l"(b), "l"(c));
    return d;
}
__device__ __forceinline__ float sum2(unsigned long long v) {
    float lo, hi;
    asm("mov.b64 {%0, %1}, %2;" : "=f"(lo), "=f"(hi) : "l"(v));
    return lo + hi;
}
__device__ __forceinline__ unsigned ld_acq(const unsigned* p) {
    unsigned v;
    asm volatile("ld.acquire.gpu.global.b32 %0, [%1];" : "=r"(v) : "l"(p));
    return v;
}
__device__ __forceinline__ void st_rel(unsigned* p, unsigned v) {
    asm volatile("st.release.gpu.global.b32 [%0], %1;" :: "l"(p), "r"(v));
}

// ---------------------------------------------------------------------------
// Phase A: xz[b,t,:] = emb[x[b,t]] @ W + bias      (M=32768, K=256, N=1024)
// 128x128 tile, 256 threads, 8x8 micro-tile (halves smem bytes per FMA).
// ---------------------------------------------------------------------------
__global__ __launch_bounds__(256) void phaseA_kernel(
    const int* __restrict__ x, const float* __restrict__ emb,
    const float* __restrict__ W, const float* __restrict__ bias)
{
    __shared__ float As[16][136];
    __shared__ float Bs[16][136];
    __shared__ int ridx[128];

    const int tid = threadIdx.x;
    const int bx = blockIdx.x;   // 0..7   (col block, 128 cols)
    const int by = blockIdx.y;   // 0..255 (row block, 128 rows)

    if (tid < 128) ridx[tid] = x[by * 128 + tid];
    __syncthreads();

    const int tx = tid & 15;     // 0..15 col group (8 cols each)
    const int ty = tid >> 4;     // 0..15 row group (8 rows each)

    float acc[8][8];
#pragma unroll
    for (int i = 0; i < 8; i++)
#pragma unroll
        for (int j = 0; j < 8; j++) acc[i][j] = 0.f;

    const int ar  = tid >> 1;            // A row this thread loads
    const int akq = (tid & 1) << 3;      // A k-offset (0 or 8)
    const int bkk = tid >> 4;            // B k-row
    const int bc8 = (tid & 15) << 3;     // B col offset

    for (int k0 = 0; k0 < 256; k0 += 16) {
        // A tile: 128 rows x 16 k (transposed into As[k][row])
        {
            const float* ap = emb + (size_t)ridx[ar] * 256 + k0 + akq;
            float4 va = *(const float4*)(ap);
            float4 vb = *(const float4*)(ap + 4);
            As[akq + 0][ar] = va.x; As[akq + 1][ar] = va.y;
            As[akq + 2][ar] = va.z; As[akq + 3][ar] = va.w;
            As[akq + 4][ar] = vb.x; As[akq + 5][ar] = vb.y;
            As[akq + 6][ar] = vb.z; As[akq + 7][ar] = vb.w;
            // B tile: 16 k x 128 cols
            const float* bp = W + (size_t)(k0 + bkk) * G4 + bx * 128 + bc8;
            *(float4*)&Bs[bkk][bc8]     = *(const float4*)(bp);
            *(float4*)&Bs[bkk][bc8 + 4] = *(const float4*)(bp + 4);
        }
        __syncthreads();
#pragma unroll
        for (int k = 0; k < 16; k++) {
            float a[8], b[8];
            float4 a0 = *(const float4*)&As[k][ty << 3];
            float4 a1 = *(const float4*)&As[k][(ty << 3) + 4];
            float4 b0 = *(const float4*)&Bs[k][tx << 3];
            float4 b1 = *(const float4*)&Bs[k][(tx << 3) + 4];
            a[0]=a0.x; a[1]=a0.y; a[2]=a0.z; a[3]=a0.w;
            a[4]=a1.x; a[5]=a1.y; a[6]=a1.z; a[7]=a1.w;
            b[0]=b0.x; b[1]=b0.y; b[2]=b0.z; b[3]=b0.w;
            b[4]=b1.x; b[5]=b1.y; b[6]=b1.z; b[7]=b1.w;
#pragma unroll
            for (int i = 0; i < 8; i++)
#pragma unroll
                for (int j = 0; j < 8; j++)
                    acc[i][j] = fmaf(a[i], b[j], acc[i][j]);
        }
        __syncthreads();
    }

    const int colbase = bx * 128 + (tx << 3);
    float4 bv0 = *(const float4*)(bias + colbase);
    float4 bv1 = *(const float4*)(bias + colbase + 4);
#pragma unroll
    for (int i = 0; i < 8; i++) {
        int row = by * 128 + (ty << 3) + i;
        float4 o0 = make_float4(acc[i][0] + bv0.x, acc[i][1] + bv0.y,
                                acc[i][2] + bv0.z, acc[i][3] + bv0.w);
        float4 o1 = make_float4(acc[i][4] + bv1.x, acc[i][5] + bv1.y,
                                acc[i][6] + bv1.z, acc[i][7] + bv1.w);
        float* op = g_xz + (size_t)row * G4 + colbase;
        *(float4*)(op)     = o0;
        *(float4*)(op + 4) = o1;
    }
}

// ---------------------------------------------------------------------------
// Phase B: 512 sequential LSTM steps, persistent grid (128 CTAs), per-bgrp
// flag barrier (no atomics). CTA (jgrp, bgrp) owns 16 batches x 8 hidden cols.
// 256 threads: warps 0-3 accumulate k[0,128), warps 4-7 k[128,256) (FFMA2),
// pair-combine through 2KB smem. U slice resident in smem all 512 steps.
// ---------------------------------------------------------------------------
#define UT_STRIDE 260   // 1040 B  (== 16 mod 128: conflict-free adjacent rows)
#define SMEM_B ((48 * UT_STRIDE) * 4 + 128 * 4 * 4)

extern __shared__ float sdyn[];

__global__ __launch_bounds__(256, 1) void phaseB_kernel(const float* __restrict__ U)
{
    float* Ut   = sdyn;                    // [32][260]  U^T slice
    float* hs   = sdyn + 32 * UT_STRIDE;   // [16][260]  h stage
    float* part = sdyn + 48 * UT_STRIDE;   // [128][4]   k-half partials

    const int tid  = threadIdx.x;          // 256
    const int jgrp = blockIdx.x;           // 0..31
    const int bgrp = blockIdx.y;           // 0..3

    // Stage U^T once: local col cl = g*8+jl  ->  global col g*256 + jgrp*8 + jl
    for (int i = tid; i < 32 * 256; i += 256) {
        int cl = i >> 8, k = i & 255;
        int g = cl >> 3, jl = cl & 7;
        Ut[cl * UT_STRIDE + k] = U[(size_t)k * G4 + g * HH + jgrp * 8 + jl];
    }

    const int half = tid >> 7;             // 0: k[0,128)  1: k[128,256)
    const int bl   = (tid >> 3) & 15;      // 0..15
    const int jl   = tid & 7;              // 0..7
    const int b    = bgrp * 16 + bl;
    const int j    = jgrp * 8 + jl;
    const int kb   = half << 7;            // k base

    float c = 0.f;
    const float* xzp = g_xz + (size_t)b * TT * G4 + j;

    const ulonglong2* u0 = (const ulonglong2*)(Ut + (0 * 8 + jl) * UT_STRIDE + kb);
    const ulonglong2* u1 = (const ulonglong2*)(Ut + (1 * 8 + jl) * UT_STRIDE + kb);
    const ulonglong2* u2 = (const ulonglong2*)(Ut + (2 * 8 + jl) * UT_STRIDE + kb);
    const ulonglong2* u3 = (const ulonglong2*)(Ut + (3 * 8 + jl) * UT_STRIDE + kb);
    const ulonglong2* hrow = (const ulonglong2*)(hs + bl * UT_STRIDE + kb);

    unsigned* flags = &g_flag[bgrp][0];
    const int mylane = tid & 31;           // peer index this thread polls
    const bool pollme = (mylane != jgrp);  // own flag always current

    __syncthreads();   // Ut ready

    for (int t = 0; t < TT; t++) {
        // prefetch xz for this step (independent of barrier; half 0 only)
        float a0 = 0.f, a1 = 0.f, a2 = 0.f, a3 = 0.f;
        if (half == 0) {
            const float* xr = xzp + (size_t)t * G4;
            a0 = __ldg(xr + 0 * HH);
            a1 = __ldg(xr + 1 * HH);
            a2 = __ldg(xr + 2 * HH);
            a3 = __ldg(xr + 3 * HH);
        }

        // wait for all 32 peers of this bgrp to have published h_{t-1}
        if (t > 0 && pollme) {
            const unsigned* f = flags + mylane * 32;
            while (ld_acq(f) < (unsigned)t) { }
        }

        // stage h (16 rows x 256) from ping-pong buffer, L1-bypassed
        const float* hsrc = g_hbuf[t & 1] + bgrp * 16 * HH;
        {
            int i = tid * 4;                       // 4096 floats / 1024 per pass
#pragma unroll
            for (int p = 0; p < 4; p++, i += 1024) {
                int r = i >> 8, k = i & 255;
                float4 v = __ldcg((const float4*)(hsrc + r * HH + k));
                *(float4*)(hs + r * UT_STRIDE + k) = v;
            }
        }
        __syncthreads();

        unsigned long long s0 = 0ull, s1 = 0ull, s2 = 0ull, s3 = 0ull;
#pragma unroll 8
        for (int k4 = 0; k4 < 32; k4++) {
            ulonglong2 hv = hrow[k4];
            ulonglong2 v0 = u0[k4];
            ulonglong2 v1 = u1[k4];
            ulonglong2 v2 = u2[k4];
            ulonglong2 v3 = u3[k4];
            s0 = ffma2(hv.x, v0.x, s0); s0 = ffma2(hv.y, v0.y, s0);
            s1 = ffma2(hv.x, v1.x, s1); s1 = ffma2(hv.y, v1.y, s1);
            s2 = ffma2(hv.x, v2.x, s2); s2 = ffma2(hv.y, v2.y, s2);
            s3 = ffma2(hv.x, v3.x, s3); s3 = ffma2(hv.y, v3.y, s3);
        }
        float p0 = sum2(s0), p1 = sum2(s1), p2 = sum2(s2), p3 = sum2(s3);

        if (half == 1)
            *(float4*)&part[(bl * 8 + jl) * 4] = make_float4(p0, p1, p2, p3);
        __syncthreads();

        if (half == 0) {
            float4 q = *(const float4*)&part[(bl * 8 + jl) * 4];
            float z0 = a0 + p0 + q.x;
            float z1 = a1 + p1 + q.y;
            float z2 = a2 + p2 + q.z;
            float z3 = a3 + p3 + q.w;
            // gates (order i, f, g, o)
            float ig = 1.f / (1.f + __expf(-z0));
            float fg = 1.f / (1.f + __expf(-z1));
            float gg = tanhf(z2);
            float og = 1.f / (1.f + __expf(-z3));
            c = fmaf(fg, c, ig * gg);
            float hn = og * tanhf(c);
            __stcg(&g_hbuf[(t + 1) & 1][b * HH + j], hn);
        }
        __syncthreads();
        if (tid == 0) st_rel(flags + jgrp * 32, (unsigned)(t + 1));
    }
}

// ---------------------------------------------------------------------------
// Phase C: logits = h_T @ Wd + bd; softmax. One warp per batch row.
// Final h lives in g_hbuf[0] (after 512 steps).
// ---------------------------------------------------------------------------
__global__ __launch_bounds__(32) void phaseC_kernel(
    const float* __restrict__ Wd, const float* __restrict__ bd,
    float* __restrict__ out)
{
    const int b = blockIdx.x;
    const int lane = threadIdx.x;
    const float* h = g_hbuf[0] + b * HH;

    float v = 0.f;
    if (lane < NCLS) {
#pragma unroll 8
        for (int k = 0; k < HH; k++)
            v = fmaf(h[k], Wd[k * NCLS + lane], v);
        v += bd[lane];
    }
    float m = (lane < NCLS) ? v : -1e30f;
#pragma unroll
    for (int o = 16; o; o >>= 1) m = fmaxf(m, __shfl_xor_sync(0xffffffffu, m, o));
    float e = (lane < NCLS) ? __expf(v - m) : 0.f;
    float s = e;
#pragma unroll
    for (int o = 16; o; o >>= 1) s += __shfl_xor_sync(0xffffffffu, s, o);
    if (lane < NCLS) out[b * NCLS + lane] = e / s;
}

// ---------------------------------------------------------------------------
extern "C" void kernel_launch(void* const* d_in, const int* in_sizes, int n_in,
                              void* d_out, int out_size)
{
    const int*   x    = (const int*)d_in[0];
    const float* emb  = (const float*)d_in[1];
    const float* W    = (const float*)d_in[2];
    const float* U    = (const float*)d_in[3];
    const float* bias = (const float*)d_in[4];
    const float* Wd   = (const float*)d_in[5];
    const float* bd   = (const float*)d_in[6];
    float* out = (float*)d_out;

    static void* hbuf_ptr = nullptr;
    static void* flag_ptr = nullptr;
    static bool inited = false;
    if (!inited) {
        cudaGetSymbolAddress(&hbuf_ptr, g_hbuf);
        cudaGetSymbolAddress(&flag_ptr, g_flag);
        cudaFuncSetAttribute(phaseB_kernel,
                             cudaFuncAttributeMaxDynamicSharedMemorySize, SMEM_B);
        inited = true;
    }

    // Reset cross-launch state (graph-capturable memset nodes)
    cudaMemsetAsync(hbuf_ptr, 0, sizeof(float) * 2 * BB * HH, 0);
    cudaMemsetAsync(flag_ptr, 0, sizeof(unsigned) * 4 * 32 * 32, 0);

    phaseA_kernel<<<dim3(8, 256), 256>>>(x, emb, W, bias);
    phaseB_kernel<<<dim3(32, 4), 256, SMEM_B>>>(U);
    phaseC_kernel<<<BB, 32>>>(Wd, bd, out);
}

// round 4
// speedup vs baseline: 1.2728x; 1.0631x over previous
#include <cuda_runtime.h>
#include <math.h>

#define BB 64        // batch
#define TT 512       // seq len
#define HH 256       // hidden
#define G4 1024      // 4*H
#define NCLS 20

// Scratch (static device globals — no runtime allocation)
__device__ float g_xz[(size_t)BB * TT * G4];   // 128 MB
__device__ float g_hbuf[2][BB * HH];
__device__ unsigned g_flag[4][32 * 32];        // flag (bgrp, jgrp) at [bgrp][jgrp*32]

// ---------------------------------------------------------------------------
// helpers
// ---------------------------------------------------------------------------
__device__ __forceinline__ unsigned long long ffma2(unsigned long long a,
                                                    unsigned long long b,
                                                    unsigned long long c) {
    unsigned long long d;
    asm("fma.rn.f32x2 %0, %1, %2, %3;" : "=l"(d) : "l"(a), "l"(b), "l"(c));
    return d;
}
__device__ __forceinline__ float sum2(unsigned long long v) {
    float lo, hi;
    asm("mov.b64 {%0, %1}, %2;" : "=f"(lo), "=f"(hi) : "l"(v));
    return lo + hi;
}
__device__ __forceinline__ unsigned ld_acq(const unsigned* p) {
    unsigned v;
    asm volatile("ld.acquire.gpu.global.b32 %0, [%1];" : "=r"(v) : "l"(p));
    return v;
}
__device__ __forceinline__ void st_rel(unsigned* p, unsigned v) {
    asm volatile("st.release.gpu.global.b32 [%0], %1;" :: "l"(p), "r"(v));
}
__device__ __forceinline__ float tanh_ap(float x) {
    float y;
    asm("tanh.approx.f32 %0, %1;" : "=f"(y) : "f"(x));
    return y;
}
__device__ __forceinline__ float sigm_ap(float x) {
    return fmaf(0.5f, tanh_ap(0.5f * x), 0.5f);
}

// ---------------------------------------------------------------------------
// Phase A: xz[b,t,:] = emb[x[b,t]] @ W + bias      (M=32768, K=256, N=1024)
// 128x128 tile, 256 threads, 8x8 micro-tile.
// ---------------------------------------------------------------------------
__global__ __launch_bounds__(256) void phaseA_kernel(
    const int* __restrict__ x, const float* __restrict__ emb,
    const float* __restrict__ W, const float* __restrict__ bias)
{
    __shared__ float As[16][136];
    __shared__ float Bs[16][136];
    __shared__ int ridx[128];

    const int tid = threadIdx.x;
    const int bx = blockIdx.x;   // 0..7   (col block, 128 cols)
    const int by = blockIdx.y;   // 0..255 (row block, 128 rows)

    if (tid < 128) ridx[tid] = x[by * 128 + tid];
    __syncthreads();

    const int tx = tid & 15;     // 0..15 col group (8 cols each)
    const int ty = tid >> 4;     // 0..15 row group (8 rows each)

    float acc[8][8];
#pragma unroll
    for (int i = 0; i < 8; i++)
#pragma unroll
        for (int j = 0; j < 8; j++) acc[i][j] = 0.f;

    const int ar  = tid >> 1;            // A row this thread loads
    const int akq = (tid & 1) << 3;      // A k-offset (0 or 8)
    const int bkk = tid >> 4;            // B k-row
    const int bc8 = (tid & 15) << 3;     // B col offset

    for (int k0 = 0; k0 < 256; k0 += 16) {
        {
            const float* ap = emb + (size_t)ridx[ar] * 256 + k0 + akq;
            float4 va = *(const float4*)(ap);
            float4 vb = *(const float4*)(ap + 4);
            As[akq + 0][ar] = va.x; As[akq + 1][ar] = va.y;
            As[akq + 2][ar] = va.z; As[akq + 3][ar] = va.w;
            As[akq + 4][ar] = vb.x; As[akq + 5][ar] = vb.y;
            As[akq + 6][ar] = vb.z; As[akq + 7][ar] = vb.w;
            const float* bp = W + (size_t)(k0 + bkk) * G4 + bx * 128 + bc8;
            *(float4*)&Bs[bkk][bc8]     = *(const float4*)(bp);
            *(float4*)&Bs[bkk][bc8 + 4] = *(const float4*)(bp + 4);
        }
        __syncthreads();
#pragma unroll
        for (int k = 0; k < 16; k++) {
            float a[8], b[8];
            float4 a0 = *(const float4*)&As[k][ty << 3];
            float4 a1 = *(const float4*)&As[k][(ty << 3) + 4];
            float4 b0 = *(const float4*)&Bs[k][tx << 3];
            float4 b1 = *(const float4*)&Bs[k][(tx << 3) + 4];
            a[0]=a0.x; a[1]=a0.y; a[2]=a0.z; a[3]=a0.w;
            a[4]=a1.x; a[5]=a1.y; a[6]=a1.z; a[7]=a1.w;
            b[0]=b0.x; b[1]=b0.y; b[2]=b0.z; b[3]=b0.w;
            b[4]=b1.x; b[5]=b1.y; b[6]=b1.z; b[7]=b1.w;
#pragma unroll
            for (int i = 0; i < 8; i++)
#pragma unroll
                for (int j = 0; j < 8; j++)
                    acc[i][j] = fmaf(a[i], b[j], acc[i][j]);
        }
        __syncthreads();
    }

    const int colbase = bx * 128 + (tx << 3);
    float4 bv0 = *(const float4*)(bias + colbase);
    float4 bv1 = *(const float4*)(bias + colbase + 4);
#pragma unroll
    for (int i = 0; i < 8; i++) {
        int row = by * 128 + (ty << 3) + i;
        float4 o0 = make_float4(acc[i][0] + bv0.x, acc[i][1] + bv0.y,
                                acc[i][2] + bv0.z, acc[i][3] + bv0.w);
        float4 o1 = make_float4(acc[i][4] + bv1.x, acc[i][5] + bv1.y,
                                acc[i][6] + bv1.z, acc[i][7] + bv1.w);
        float* op = g_xz + (size_t)row * G4 + colbase;
        *(float4*)(op)     = o0;
        *(float4*)(op + 4) = o1;
    }
}

// ---------------------------------------------------------------------------
// Phase B: 512 sequential LSTM steps, persistent grid (128 CTAs), per-bgrp
// flag barrier. CTA (jgrp, bgrp) owns 16 batches x 8 hidden cols.
// 512 threads: quarter q accumulates k in [q*64, q*64+64) with FFMA2.
// Staging: warp w pulls peers {w, w+16} (spin flag -> ldcg piece -> STS),
// pipelining flag detection with data fetch across the 32 peers.
// ---------------------------------------------------------------------------
#define UT_STRIDE 260   // 1040 B rows (16B aligned, conflict-free layout)
#define SMEM_B ((48 * UT_STRIDE) * 4 + 3 * 128 * 4 * 4)

extern __shared__ float sdyn[];

__global__ __launch_bounds__(512, 1) void phaseB_kernel(const float* __restrict__ U)
{
    float* Ut   = sdyn;                    // [32][260]  U^T slice (resident)
    float* hs   = sdyn + 32 * UT_STRIDE;   // [16][260]  h stage
    float* part = sdyn + 48 * UT_STRIDE;   // [3][128][4] quarter partials

    const int tid  = threadIdx.x;          // 512
    const int jgrp = blockIdx.x;           // 0..31
    const int bgrp = blockIdx.y;           // 0..3

    // Stage U^T once: local col cl = g*8+jl  ->  global col g*256 + jgrp*8 + jl
    for (int i = tid; i < 32 * 256; i += 512) {
        int cl = i >> 8, k = i & 255;
        int g = cl >> 3, jl = cl & 7;
        Ut[cl * UT_STRIDE + k] = U[(size_t)k * G4 + g * HH + jgrp * 8 + jl];
    }
    // zero h stage (h_0 = 0); staging is skipped at t==0
    for (int i = tid; i < 16 * UT_STRIDE; i += 512) hs[i] = 0.f;

    const int quarter = tid >> 7;          // 0..3 : k quarter
    const int cell    = tid & 127;         // (bl, jl)
    const int bl      = cell >> 3;         // 0..15
    const int jl      = cell & 7;          // 0..7
    const int b       = bgrp * 16 + bl;
    const int j       = jgrp * 8 + jl;
    const int kb      = quarter << 6;      // k base (floats)

    const int wid  = tid >> 5;             // 0..15
    const int lane = tid & 31;

    float c = 0.f;
    const float* xzp = g_xz + (size_t)b * TT * G4 + j;

    const ulonglong2* u0 = (const ulonglong2*)(Ut + (0 * 8 + jl) * UT_STRIDE + kb);
    const ulonglong2* u1 = (const ulonglong2*)(Ut + (1 * 8 + jl) * UT_STRIDE + kb);
    const ulonglong2* u2 = (const ulonglong2*)(Ut + (2 * 8 + jl) * UT_STRIDE + kb);
    const ulonglong2* u3 = (const ulonglong2*)(Ut + (3 * 8 + jl) * UT_STRIDE + kb);
    const ulonglong2* hrow = (const ulonglong2*)(hs + bl * UT_STRIDE + kb);

    unsigned* flags = &g_flag[bgrp][0];
    // staging: warp wid handles peers wid and wid+16; lane r covers
    // row r>>1 (of 16), half r&1 (float4) of the 16x8 piece.
    const int srow = lane >> 1;
    const int shalf = (lane & 1) << 2;

    __syncthreads();   // Ut + hs ready

    for (int t = 0; t < TT; t++) {
        // prefetch xz for this step (quarter 0 only; independent of staging)
        float a0 = 0.f, a1 = 0.f, a2 = 0.f, a3 = 0.f;
        if (quarter == 0) {
            const float* xr = xzp + (size_t)t * G4;
            a0 = __ldg(xr + 0 * HH);
            a1 = __ldg(xr + 1 * HH);
            a2 = __ldg(xr + 2 * HH);
            a3 = __ldg(xr + 3 * HH);
        }

        if (t > 0) {
            // per-peer pipelined staging of h_t pieces
            const float* hsrc = g_hbuf[t & 1] + bgrp * 16 * HH;
#pragma unroll
            for (int pp = 0; pp < 2; pp++) {
                int p = wid + pp * 16;
                const unsigned* f = flags + p * 32;
                while (ld_acq(f) < (unsigned)t) { }
                float4 v = __ldcg((const float4*)(hsrc + srow * HH + p * 8 + shalf));
                *(float4*)(hs + srow * UT_STRIDE + p * 8 + shalf) = v;
            }
        }
        __syncthreads();

        unsigned long long s0 = 0ull, s1 = 0ull, s2 = 0ull, s3 = 0ull;
#pragma unroll 4
        for (int k4 = 0; k4 < 16; k4++) {
            ulonglong2 hv = hrow[k4];
            ulonglong2 v0 = u0[k4];
            ulonglong2 v1 = u1[k4];
            ulonglong2 v2 = u2[k4];
            ulonglong2 v3 = u3[k4];
            s0 = ffma2(hv.x, v0.x, s0); s0 = ffma2(hv.y, v0.y, s0);
            s1 = ffma2(hv.x, v1.x, s1); s1 = ffma2(hv.y, v1.y, s1);
            s2 = ffma2(hv.x, v2.x, s2); s2 = ffma2(hv.y, v2.y, s2);
            s3 = ffma2(hv.x, v3.x, s3); s3 = ffma2(hv.y, v3.y, s3);
        }
        float p0 = sum2(s0), p1 = sum2(s1), p2 = sum2(s2), p3 = sum2(s3);

        if (quarter != 0)
            *(float4*)&part[((quarter - 1) * 128 + cell) * 4] =
                make_float4(p0, p1, p2, p3);
        __syncthreads();

        if (quarter == 0) {
            float4 q1 = *(const float4*)&part[(0 * 128 + cell) * 4];
            float4 q2 = *(const float4*)&part[(1 * 128 + cell) * 4];
            float4 q3 = *(const float4*)&part[(2 * 128 + cell) * 4];
            float z0 = a0 + p0 + q1.x + q2.x + q3.x;
            float z1 = a1 + p1 + q1.y + q2.y + q3.y;
            float z2 = a2 + p2 + q1.z + q2.z + q3.z;
            float z3 = a3 + p3 + q1.w + q2.w + q3.w;
            // gates (order i, f, g, o)
            float ig = sigm_ap(z0);
            float fg = sigm_ap(z1);
            float gg = tanh_ap(z2);
            float og = sigm_ap(z3);
            c = fmaf(fg, c, ig * gg);
            float hn = og * tanh_ap(c);
            __stcg(&g_hbuf[(t + 1) & 1][b * HH + j], hn);
            // half-CTA barrier: all 128 quarter-0 threads' stores done
            asm volatile("bar.sync 1, 128;" ::: "memory");
            if (tid == 0) st_rel(flags + jgrp * 32, (unsigned)(t + 1));
        }
        // other quarters proceed straight to next-iteration staging
    }
}

// ---------------------------------------------------------------------------
// Phase C: logits = h_T @ Wd + bd; softmax. One warp per batch row.
// Final h lives in g_hbuf[0] (512 steps -> buf (511+1)&1 == 0).
// ---------------------------------------------------------------------------
__global__ __launch_bounds__(32) void phaseC_kernel(
    const float* __restrict__ Wd, const float* __restrict__ bd,
    float* __restrict__ out)
{
    const int b = blockIdx.x;
    const int lane = threadIdx.x;
    const float* h = g_hbuf[0] + b * HH;

    float v = 0.f;
    if (lane < NCLS) {
#pragma unroll 8
        for (int k = 0; k < HH; k++)
            v = fmaf(h[k], Wd[k * NCLS + lane], v);
        v += bd[lane];
    }
    float m = (lane < NCLS) ? v : -1e30f;
#pragma unroll
    for (int o = 16; o; o >>= 1) m = fmaxf(m, __shfl_xor_sync(0xffffffffu, m, o));
    float e = (lane < NCLS) ? __expf(v - m) : 0.f;
    float s = e;
#pragma unroll
    for (int o = 16; o; o >>= 1) s += __shfl_xor_sync(0xffffffffu, s, o);
    if (lane < NCLS) out[b * NCLS + lane] = e / s;
}

// ---------------------------------------------------------------------------
extern "C" void kernel_launch(void* const* d_in, const int* in_sizes, int n_in,
                              void* d_out, int out_size)
{
    const int*   x    = (const int*)d_in[0];
    const float* emb  = (const float*)d_in[1];
    const float* W    = (const float*)d_in[2];
    const float* U    = (const float*)d_in[3];
    const float* bias = (const float*)d_in[4];
    const float* Wd   = (const float*)d_in[5];
    const float* bd   = (const float*)d_in[6];
    float* out = (float*)d_out;

    static void* flag_ptr = nullptr;
    static bool inited = false;
    if (!inited) {
        cudaGetSymbolAddress(&flag_ptr, g_flag);
        cudaFuncSetAttribute(phaseB_kernel,
                             cudaFuncAttributeMaxDynamicSharedMemorySize, SMEM_B);
        inited = true;
    }

    // Reset cross-launch flag state (graph-capturable memset node)
    cudaMemsetAsync(flag_ptr, 0, sizeof(unsigned) * 4 * 32 * 32, 0);

    phaseA_kernel<<<dim3(8, 256), 256>>>(x, emb, W, bias);
    phaseB_kernel<<<dim3(32, 4), 512, SMEM_B>>>(U);
    phaseC_kernel<<<BB, 32>>>(Wd, bd, out);
}

// round 5
// speedup vs baseline: 1.3074x; 1.0272x over previous
#include <cuda_runtime.h>
#include <math.h>

#define BB 64        // batch
#define TT 512       // seq len
#define HH 256       // hidden
#define G4 1024      // 4*H
#define NCLS 20

// Scratch (static device globals — no runtime allocation)
__device__ float g_xz[(size_t)BB * TT * G4];   // 128 MB
__device__ float g_hbuf[2][BB * HH];
__device__ unsigned g_flag[4][32 * 32];        // flag (bgrp, jgrp) at [bgrp][jgrp*32]

// ---------------------------------------------------------------------------
// helpers
// ---------------------------------------------------------------------------
__device__ __forceinline__ unsigned long long ffma2(unsigned long long a,
                                                    unsigned long long b,
                                                    unsigned long long c) {
    unsigned long long d;
    asm("fma.rn.f32x2 %0, %1, %2, %3;" : "=l"(d) : "l"(a), "l"(b), "l"(c));
    return d;
}
__device__ __forceinline__ float sum2(unsigned long long v) {
    float lo, hi;
    asm("mov.b64 {%0, %1}, %2;" : "=f"(lo), "=f"(hi) : "l"(v));
    return lo + hi;
}
__device__ __forceinline__ unsigned ld_acq(const unsigned* p) {
    unsigned v;
    asm volatile("ld.acquire.gpu.global.b32 %0, [%1];" : "=r"(v) : "l"(p));
    return v;
}
__device__ __forceinline__ void st_rel(unsigned* p, unsigned v) {
    asm volatile("st.release.gpu.global.b32 [%0], %1;" :: "l"(p), "r"(v));
}
__device__ __forceinline__ float tanh_ap(float x) {
    float y;
    asm("tanh.approx.f32 %0, %1;" : "=f"(y) : "f"(x));
    return y;
}
__device__ __forceinline__ float sigm_ap(float x) {
    return fmaf(0.5f, tanh_ap(0.5f * x), 0.5f);
}

// ---------------------------------------------------------------------------
// Phase A: xz[b,t,:] = emb[x[b,t]] @ W + bias      (M=32768, K=256, N=1024)
// 128x128 tile, 256 threads, 8x8 micro-tile.
// ---------------------------------------------------------------------------
__global__ __launch_bounds__(256) void phaseA_kernel(
    const int* __restrict__ x, const float* __restrict__ emb,
    const float* __restrict__ W, const float* __restrict__ bias)
{
    __shared__ float As[16][136];
    __shared__ float Bs[16][136];
    __shared__ int ridx[128];

    const int tid = threadIdx.x;
    const int bx = blockIdx.x;   // 0..7   (col block, 128 cols)
    const int by = blockIdx.y;   // 0..255 (row block, 128 rows)

    if (tid < 128) ridx[tid] = x[by * 128 + tid];
    __syncthreads();

    const int tx = tid & 15;     // 0..15 col group (8 cols each)
    const int ty = tid >> 4;     // 0..15 row group (8 rows each)

    float acc[8][8];
#pragma unroll
    for (int i = 0; i < 8; i++)
#pragma unroll
        for (int j = 0; j < 8; j++) acc[i][j] = 0.f;

    const int ar  = tid >> 1;            // A row this thread loads
    const int akq = (tid & 1) << 3;      // A k-offset (0 or 8)
    const int bkk = tid >> 4;            // B k-row
    const int bc8 = (tid & 15) << 3;     // B col offset

    for (int k0 = 0; k0 < 256; k0 += 16) {
        {
            const float* ap = emb + (size_t)ridx[ar] * 256 + k0 + akq;
            float4 va = *(const float4*)(ap);
            float4 vb = *(const float4*)(ap + 4);
            As[akq + 0][ar] = va.x; As[akq + 1][ar] = va.y;
            As[akq + 2][ar] = va.z; As[akq + 3][ar] = va.w;
            As[akq + 4][ar] = vb.x; As[akq + 5][ar] = vb.y;
            As[akq + 6][ar] = vb.z; As[akq + 7][ar] = vb.w;
            const float* bp = W + (size_t)(k0 + bkk) * G4 + bx * 128 + bc8;
            *(float4*)&Bs[bkk][bc8]     = *(const float4*)(bp);
            *(float4*)&Bs[bkk][bc8 + 4] = *(const float4*)(bp + 4);
        }
        __syncthreads();
#pragma unroll
        for (int k = 0; k < 16; k++) {
            float a[8], b[8];
            float4 a0 = *(const float4*)&As[k][ty << 3];
            float4 a1 = *(const float4*)&As[k][(ty << 3) + 4];
            float4 b0 = *(const float4*)&Bs[k][tx << 3];
            float4 b1 = *(const float4*)&Bs[k][(tx << 3) + 4];
            a[0]=a0.x; a[1]=a0.y; a[2]=a0.z; a[3]=a0.w;
            a[4]=a1.x; a[5]=a1.y; a[6]=a1.z; a[7]=a1.w;
            b[0]=b0.x; b[1]=b0.y; b[2]=b0.z; b[3]=b0.w;
            b[4]=b1.x; b[5]=b1.y; b[6]=b1.z; b[7]=b1.w;
#pragma unroll
            for (int i = 0; i < 8; i++)
#pragma unroll
                for (int j = 0; j < 8; j++)
                    acc[i][j] = fmaf(a[i], b[j], acc[i][j]);
        }
        __syncthreads();
    }

    const int colbase = bx * 128 + (tx << 3);
    float4 bv0 = *(const float4*)(bias + colbase);
    float4 bv1 = *(const float4*)(bias + colbase + 4);
#pragma unroll
    for (int i = 0; i < 8; i++) {
        int row = by * 128 + (ty << 3) + i;
        float4 o0 = make_float4(acc[i][0] + bv0.x, acc[i][1] + bv0.y,
                                acc[i][2] + bv0.z, acc[i][3] + bv0.w);
        float4 o1 = make_float4(acc[i][4] + bv1.x, acc[i][5] + bv1.y,
                                acc[i][6] + bv1.z, acc[i][7] + bv1.w);
        float* op = g_xz + (size_t)row * G4 + colbase;
        *(float4*)(op)     = o0;
        *(float4*)(op + 4) = o1;
    }
}

// ---------------------------------------------------------------------------
// Phase B: 512 sequential LSTM steps, persistent grid (128 CTAs), per-bgrp
// flag barrier. CTA (jgrp, bgrp) owns 16 batches x 8 hidden cols.
// 512 threads: quarter q accumulates k in [q*64, q*64+64) with FFMA2.
// Staging: warp w handles peers {w, w+16} FULLY IN PARALLEL — lanes 0-15
// poll/fetch peer w, lanes 16-31 poll/fetch peer w+16, single combined spin.
// ---------------------------------------------------------------------------
#define UT_STRIDE 260   // 1040 B rows (16B aligned)
#define SMEM_B ((48 * UT_STRIDE) * 4 + 3 * 128 * 4 * 4)

extern __shared__ float sdyn[];

__global__ __launch_bounds__(512, 1) void phaseB_kernel(const float* __restrict__ U)
{
    float* Ut   = sdyn;                    // [32][260]  U^T slice (resident)
    float* hs   = sdyn + 32 * UT_STRIDE;   // [16][260]  h stage
    float* part = sdyn + 48 * UT_STRIDE;   // [3][128][4] quarter partials

    const int tid  = threadIdx.x;          // 512
    const int jgrp = blockIdx.x;           // 0..31
    const int bgrp = blockIdx.y;           // 0..3

    // Stage U^T once: local col cl = g*8+jl  ->  global col g*256 + jgrp*8 + jl
    for (int i = tid; i < 32 * 256; i += 512) {
        int cl = i >> 8, k = i & 255;
        int g = cl >> 3, jl = cl & 7;
        Ut[cl * UT_STRIDE + k] = U[(size_t)k * G4 + g * HH + jgrp * 8 + jl];
    }
    // zero h stage (h_0 = 0); staging is skipped at t==0
    for (int i = tid; i < 16 * UT_STRIDE; i += 512) hs[i] = 0.f;

    const int quarter = tid >> 7;          // 0..3 : k quarter
    const int cell    = tid & 127;         // (bl, jl)
    const int bl      = cell >> 3;         // 0..15
    const int jl      = cell & 7;          // 0..7
    const int b       = bgrp * 16 + bl;
    const int j       = jgrp * 8 + jl;
    const int kb      = quarter << 6;      // k base (floats)

    const int wid  = tid >> 5;             // 0..15
    const int lane = tid & 31;

    float c = 0.f;
    const float* xzp = g_xz + (size_t)b * TT * G4 + j;

    const ulonglong2* u0 = (const ulonglong2*)(Ut + (0 * 8 + jl) * UT_STRIDE + kb);
    const ulonglong2* u1 = (const ulonglong2*)(Ut + (1 * 8 + jl) * UT_STRIDE + kb);
    const ulonglong2* u2 = (const ulonglong2*)(Ut + (2 * 8 + jl) * UT_STRIDE + kb);
    const ulonglong2* u3 = (const ulonglong2*)(Ut + (3 * 8 + jl) * UT_STRIDE + kb);
    const ulonglong2* hrow = (const ulonglong2*)(hs + bl * UT_STRIDE + kb);

    unsigned* flags = &g_flag[bgrp][0];
    // staging assignment: lane-half selects one of this warp's two peers;
    // within a half, lane covers one of the 16 rows of the 16x8 piece.
    const int speer = (lane >> 4) ? (wid + 16) : wid;   // peer CTA index
    const int srow  = lane & 15;                        // row 0..15
    const unsigned* sflag = flags + speer * 32;

    __syncthreads();   // Ut + hs ready

    for (int t = 0; t < TT; t++) {
        // prefetch xz for this step (quarter 0 only; issued before any wait)
        float a0 = 0.f, a1 = 0.f, a2 = 0.f, a3 = 0.f;
        if (quarter == 0) {
            const float* xr = xzp + (size_t)t * G4;
            a0 = __ldg(xr + 0 * HH);
            a1 = __ldg(xr + 1 * HH);
            a2 = __ldg(xr + 2 * HH);
            a3 = __ldg(xr + 3 * HH);
        }

        if (t > 0) {
            // parallel detect of both peers, then parallel fetch
            while (!__all_sync(0xffffffffu, ld_acq(sflag) >= (unsigned)t)) { }
            const float* src = g_hbuf[t & 1] + (bgrp * 16 + srow) * HH + speer * 8;
            float4 v0 = __ldcg((const float4*)(src));
            float4 v1 = __ldcg((const float4*)(src + 4));
            float* dst = hs + srow * UT_STRIDE + speer * 8;
            *(float4*)(dst)     = v0;
            *(float4*)(dst + 4) = v1;
        }
        __syncthreads();

        unsigned long long s0 = 0ull, s1 = 0ull, s2 = 0ull, s3 = 0ull;
#pragma unroll 4
        for (int k4 = 0; k4 < 16; k4++) {
            ulonglong2 hv = hrow[k4];
            ulonglong2 v0 = u0[k4];
            ulonglong2 v1 = u1[k4];
            ulonglong2 v2 = u2[k4];
            ulonglong2 v3 = u3[k4];
            s0 = ffma2(hv.x, v0.x, s0); s0 = ffma2(hv.y, v0.y, s0);
            s1 = ffma2(hv.x, v1.x, s1); s1 = ffma2(hv.y, v1.y, s1);
            s2 = ffma2(hv.x, v2.x, s2); s2 = ffma2(hv.y, v2.y, s2);
            s3 = ffma2(hv.x, v3.x, s3); s3 = ffma2(hv.y, v3.y, s3);
        }
        float p0 = sum2(s0), p1 = sum2(s1), p2 = sum2(s2), p3 = sum2(s3);

        if (quarter != 0) {
            *(float4*)&part[((quarter - 1) * 128 + cell) * 4] =
                make_float4(p0, p1, p2, p3);
            // producers arrive and run ahead to next step's staging
            asm volatile("bar.arrive 2, 512;" ::: "memory");
        } else {
            asm volatile("bar.sync 2, 512;" ::: "memory");
            float4 q1 = *(const float4*)&part[(0 * 128 + cell) * 4];
            float4 q2 = *(const float4*)&part[(1 * 128 + cell) * 4];
            float4 q3 = *(const float4*)&part[(2 * 128 + cell) * 4];
            float z0 = a0 + p0 + q1.x + q2.x + q3.x;
            float z1 = a1 + p1 + q1.y + q2.y + q3.y;
            float z2 = a2 + p2 + q1.z + q2.z + q3.z;
            float z3 = a3 + p3 + q1.w + q2.w + q3.w;
            // gates (order i, f, g, o)
            float ig = sigm_ap(z0);
            float fg = sigm_ap(z1);
            float gg = tanh_ap(z2);
            float og = sigm_ap(z3);
            c = fmaf(fg, c, ig * gg);
            float hn = og * tanh_ap(c);
            __stcg(&g_hbuf[(t + 1) & 1][b * HH + j], hn);
            // quarter-0 barrier: all 128 h stores issued & ordered
            asm volatile("bar.sync 1, 128;" ::: "memory");
            if (tid == 0) st_rel(flags + jgrp * 32, (unsigned)(t + 1));
        }
    }
}

// ---------------------------------------------------------------------------
// Phase C: logits = h_T @ Wd + bd; softmax. One warp per batch row.
// Final h lives in g_hbuf[0] (512 steps -> buf (511+1)&1 == 0).
// ---------------------------------------------------------------------------
__global__ __launch_bounds__(32) void phaseC_kernel(
    const float* __restrict__ Wd, const float* __restrict__ bd,
    float* __restrict__ out)
{
    const int b = blockIdx.x;
    const int lane = threadIdx.x;
    const float* h = g_hbuf[0] + b * HH;

    float v = 0.f;
    if (lane < NCLS) {
#pragma unroll 8
        for (int k = 0; k < HH; k++)
            v = fmaf(h[k], Wd[k * NCLS + lane], v);
        v += bd[lane];
    }
    float m = (lane < NCLS) ? v : -1e30f;
#pragma unroll
    for (int o = 16; o; o >>= 1) m = fmaxf(m, __shfl_xor_sync(0xffffffffu, m, o));
    float e = (lane < NCLS) ? __expf(v - m) : 0.f;
    float s = e;
#pragma unroll
    for (int o = 16; o; o >>= 1) s += __shfl_xor_sync(0xffffffffu, s, o);
    if (lane < NCLS) out[b * NCLS + lane] = e / s;
}

// ---------------------------------------------------------------------------
extern "C" void kernel_launch(void* const* d_in, const int* in_sizes, int n_in,
                              void* d_out, int out_size)
{
    const int*   x    = (const int*)d_in[0];
    const float* emb  = (const float*)d_in[1];
    const float* W    = (const float*)d_in[2];
    const float* U    = (const float*)d_in[3];
    const float* bias = (const float*)d_in[4];
    const float* Wd   = (const float*)d_in[5];
    const float* bd   = (const float*)d_in[6];
    float* out = (float*)d_out;

    static void* flag_ptr = nullptr;
    static bool inited = false;
    if (!inited) {
        cudaGetSymbolAddress(&flag_ptr, g_flag);
        cudaFuncSetAttribute(phaseB_kernel,
                             cudaFuncAttributeMaxDynamicSharedMemorySize, SMEM_B);
        inited = true;
    }

    // Reset cross-launch flag state (graph-capturable memset node)
    cudaMemsetAsync(flag_ptr, 0, sizeof(unsigned) * 4 * 32 * 32, 0);

    phaseA_kernel<<<dim3(8, 256), 256>>>(x, emb, W, bias);
    phaseB_kernel<<<dim3(32, 4), 512, SMEM_B>>>(U);
    phaseC_kernel<<<BB, 32>>>(Wd, bd, out);
}